// round 7
// baseline (speedup 1.0000x reference)
#include <cuda_runtime.h>
#include <cstdint>

// Binarized NAND-conv net. EIGHT threads per image, split by spatial position.
// L0 is computed ARITHMETICALLY (bitwise 2-of-4 majority across all 16
// channels at once) -> zero shuffles in the mainloop.
//  L0: 1x28x28 ->16x14x14 (T=4)  L1: ->16x7x7  L2: ->16x6x6
//  L3: ->16x3x3  L4: ->16x1x1 (T=64)  L5: ->10 (T=16)
//  bit=1 <=> +1 ; out bit = (#mismatch >= T/2).

#define NTHREADS 256
#define IMGS_PER_BLOCK 32            // 8 threads per image
#define NWORDS (IMGS_PER_BLOCK * 784 / 32)   // 784
#define S1 53
#define S2 37
#define S3 13
#define FULL 0xFFFFFFFFu

__device__ __forceinline__ uint32_t nand16(uint64_t a, const uint64_t (&W)[16]) {
    uint32_t acc = 0;
#pragma unroll
    for (int oc = 0; oc < 16; oc++) {
        uint64_t x = a ^ W[oc];
        uint32_t D = __popc((uint32_t)x) + __popc((uint32_t)(x >> 32)) + 32;
        acc |= (D >> 6) << oc;   // 1 iff mismatches >= 32 (D in [32,96])
    }
    return acc;
}

// L0 cell: 2x2 input patch (rows rA,rB at columns cc,cc+1) vs all 16 channel
// weights simultaneously. Returns 16-bit channel vector (upper bits garbage).
// m_k = per-channel mismatch mask of tap k; output = (#mismatch >= 2).
__device__ __forceinline__ uint32_t cell16(uint32_t rA, uint32_t rB, int cc,
                                           uint32_t W00, uint32_t W01,
                                           uint32_t W02, uint32_t W03) {
    uint32_t m0 = W00 ^ (uint32_t)(((int)(rA << (31 - cc))) >> 31);
    uint32_t m1 = W01 ^ (uint32_t)(((int)(rA << (30 - cc))) >> 31);
    uint32_t m2 = W02 ^ (uint32_t)(((int)(rB << (31 - cc))) >> 31);
    uint32_t m3 = W03 ^ (uint32_t)(((int)(rB << (30 - cc))) >> 31);
    return (m0 & m1) | (m2 & m3) | ((m0 ^ m1) & (m2 ^ m3));
}

__global__ void __launch_bounds__(NTHREADS, 3)
bnn_mnist_kernel(const float* __restrict__ x,
                 const float* __restrict__ w0, const float* __restrict__ w1,
                 const float* __restrict__ w2, const float* __restrict__ w3,
                 const float* __restrict__ w4, const float* __restrict__ w5,
                 float* __restrict__ out, int B)
{
    __shared__ uint32_t sbits[NWORDS + 1];
    __shared__ uint64_t sw_sh[4][16];
    __shared__ uint32_t sw0t[4];     // tap-k weight bit per channel, 16-bit masks
    __shared__ uint32_t sw5s[10];
    __shared__ uint32_t sact1[IMGS_PER_BLOCK * S1];
    __shared__ uint32_t sact2[IMGS_PER_BLOCK * S2];
    __shared__ uint32_t sact3[IMGS_PER_BLOCK * S3];

    const int tid = threadIdx.x;
    const int lane = tid & 31;
    const int b0 = blockIdx.x * IMGS_PER_BLOCK;

    // ---- weight prep ----
    if (tid < 64) {
        int L = tid >> 4, oc = tid & 15;
        const float* wp = (L == 0 ? w1 : L == 1 ? w2 : L == 2 ? w3 : w4) + oc * 64;
        uint64_t v = 0;
#pragma unroll
        for (int ic = 0; ic < 16; ic++)
#pragma unroll
            for (int tap = 0; tap < 4; tap++)
                if (wp[ic * 4 + tap] > 0.0f) v |= 1ull << (tap * 16 + ic);
        sw_sh[L][oc] = v;
    } else if (tid < 68) {
        int k = tid - 64;
        uint32_t v = 0;
#pragma unroll
        for (int c = 0; c < 16; c++)
            if (w0[c * 4 + k] > 0.0f) v |= 1u << c;
        sw0t[k] = v;
    } else if (tid < 78) {
        int c = tid - 68;
        uint32_t v = 0;
#pragma unroll
        for (int ic = 0; ic < 16; ic++)
            if (w5[c * 16 + ic] > 0.0f) v |= 1u << ic;
        sw5s[c] = v;
    } else if (tid == 78) {
        sbits[NWORDS] = 0;
    }

    // ---- load + binarize + pack ----
    {
        const int warp = tid >> 5;
        const float* chunk = x + (size_t)b0 * 784;
        if (b0 + IMGS_PER_BLOCK <= B) {
            const float4* c4 = (const float4*)chunk;
            for (int ch = warp; ch < NWORDS / 4; ch += (NTHREADS / 32)) {
                float4 v = c4[ch * 32 + lane];
                uint32_t nib = (uint32_t)(v.x > 0.0f) | ((uint32_t)(v.y > 0.0f) << 1)
                             | ((uint32_t)(v.z > 0.0f) << 2) | ((uint32_t)(v.w > 0.0f) << 3);
                uint32_t val = nib << (4 * (lane & 7));
                val |= __shfl_xor_sync(FULL, val, 1);
                val |= __shfl_xor_sync(FULL, val, 2);
                val |= __shfl_xor_sync(FULL, val, 4);
                if ((lane & 7) == 0) sbits[ch * 4 + (lane >> 3)] = val;
            }
        } else {
            const int nfloats = max(min(IMGS_PER_BLOCK, B - b0), 0) * 784;
            for (int w = warp; w < NWORDS; w += (NTHREADS / 32)) {
                int f = w * 32 + lane;
                float v = (f < nfloats) ? chunk[f] : 0.0f;
                unsigned bb = __ballot_sync(FULL, v > 0.0f);
                if (lane == 0) sbits[w] = bb;
            }
        }
    }
    __syncthreads();

    const int sub  = tid & 7;          // 0..7: sub-worker within image
    const int limg = tid >> 3;         // 0..31: block-local image
    const int img  = b0 + limg;
    const int bitbase = limg * 784;
    const int row1 = limg * S1;
    const int row2 = limg * S2;
    const int row3 = limg * S3;

    const uint32_t W00 = sw0t[0], W01 = sw0t[1], W02 = sw0t[2], W03 = sw0t[3];

    uint64_t W[16];

    // ---- L0+L1: output row i = sub (sub 7 idle; no shfl -> divergence OK) ----
#pragma unroll
    for (int k = 0; k < 16; k++) W[k] = sw_sh[0][k];
    if (sub < 7) {
        const int i = sub;
        const int r0 = bitbase + 112 * i;   // input row 4i
        int bp = r0;
        uint32_t rA0 = __funnelshift_r(sbits[bp >> 5], sbits[(bp >> 5) + 1], bp);
        bp = r0 + 28;
        uint32_t rB0 = __funnelshift_r(sbits[bp >> 5], sbits[(bp >> 5) + 1], bp);
        bp = r0 + 56;
        uint32_t rA1 = __funnelshift_r(sbits[bp >> 5], sbits[(bp >> 5) + 1], bp);
        bp = r0 + 84;
        uint32_t rB1 = __funnelshift_r(sbits[bp >> 5], sbits[(bp >> 5) + 1], bp);
#pragma unroll
        for (int j = 0; j < 7; j++) {
            const int cc = 4 * j;
            uint32_t v00 = cell16(rA0, rB0, cc,     W00, W01, W02, W03) & 0xFFFFu;
            uint32_t v01 = cell16(rA0, rB0, cc + 2, W00, W01, W02, W03) & 0xFFFFu;
            uint32_t v10 = cell16(rA1, rB1, cc,     W00, W01, W02, W03) & 0xFFFFu;
            uint32_t v11 = cell16(rA1, rB1, cc + 2, W00, W01, W02, W03) & 0xFFFFu;
            uint64_t a64 = (uint64_t)(v00 | (v01 << 16))
                         | ((uint64_t)(v10 | (v11 << 16)) << 32);
            sact1[row1 + i * 7 + j] = nand16(a64, W);
        }
    }
    __syncwarp();

    // ---- L2: 7x7 -> 6x6; 36 positions dealt p = sub + 8k ----
#pragma unroll
    for (int k = 0; k < 16; k++) W[k] = sw_sh[1][k];
#pragma unroll
    for (int k = 0; k < 5; k++) {
        const int p = sub + 8 * k;
        if (p < 36) {
            const int i = p / 6;
            const int q = row1 + p + i;      // i*7 + j
            uint64_t a64 = (uint64_t)sact1[q] | ((uint64_t)sact1[q + 1] << 16)
                         | ((uint64_t)sact1[q + 7] << 32) | ((uint64_t)sact1[q + 8] << 48);
            sact2[row2 + p] = nand16(a64, W);
        }
    }
    __syncwarp();

    // ---- L3: 6x6 -> 3x3; 9 positions: p = sub + 8k ----
#pragma unroll
    for (int k = 0; k < 16; k++) W[k] = sw_sh[2][k];
#pragma unroll
    for (int k = 0; k < 2; k++) {
        const int p = sub + 8 * k;
        if (p < 9) {
            const int i = p / 3;
            const int j = p - 3 * i;
            const int q = row2 + 12 * i + 2 * j;
            uint64_t a64 = (uint64_t)sact2[q] | ((uint64_t)sact2[q + 1] << 16)
                         | ((uint64_t)sact2[q + 6] << 32) | ((uint64_t)sact2[q + 7] << 48);
            sact3[row3 + p] = nand16(a64, W);
        }
    }
    __syncwarp();

    // ---- L4: 1 position; 2 ocs per sub, merge via shfl_xor OR (8-lane group) ----
    uint32_t act4;
    {
        uint64_t a4 = (uint64_t)sact3[row3 + 0] | ((uint64_t)sact3[row3 + 1] << 16)
                    | ((uint64_t)sact3[row3 + 3] << 32) | ((uint64_t)sact3[row3 + 4] << 48);
        uint32_t acc = 0;
#pragma unroll
        for (int m = 0; m < 2; m++) {
            const int oc = sub * 2 + m;
            uint64_t xx = a4 ^ sw_sh[3][oc];
            uint32_t D = __popc((uint32_t)xx) + __popc((uint32_t)(xx >> 32)) + 32;
            acc |= (D >> 6) << oc;
        }
        acc |= __shfl_xor_sync(FULL, acc, 1);
        acc |= __shfl_xor_sync(FULL, acc, 2);
        acc |= __shfl_xor_sync(FULL, acc, 4);
        act4 = acc;
    }

    // ---- L5: classes dealt per sub: sub, sub+8 (<10) ----
    if (img < B) {
        float* o = out + (size_t)img * 10;
        {
            uint32_t D = __popc((act4 ^ sw5s[sub]) & 0xFFFFu);
            o[sub] = (D >= 8) ? 1.0f : -1.0f;
        }
        if (sub < 2) {
            const int oc = sub + 8;
            uint32_t D = __popc((act4 ^ sw5s[oc]) & 0xFFFFu);
            o[oc] = (D >= 8) ? 1.0f : -1.0f;
        }
    }
}

extern "C" void kernel_launch(void* const* d_in, const int* in_sizes, int n_in,
                              void* d_out, int out_size)
{
    const float* x  = (const float*)d_in[0];
    const float* w0 = (const float*)d_in[1];
    const float* w1 = (const float*)d_in[2];
    const float* w2 = (const float*)d_in[3];
    const float* w3 = (const float*)d_in[4];
    const float* w4 = (const float*)d_in[5];
    const float* w5 = (const float*)d_in[6];
    float* out = (float*)d_out;

    int B = in_sizes[0] / 784;
    int grid = (B + IMGS_PER_BLOCK - 1) / IMGS_PER_BLOCK;
    bnn_mnist_kernel<<<grid, NTHREADS>>>(x, w0, w1, w2, w3, w4, w5, out, B);
}

// round 8
// speedup vs baseline: 1.2250x; 1.2250x over previous
#include <cuda_runtime.h>
#include <cstdint>

// Binarized NAND-conv net. 4 threads per image (position split), arithmetic
// L0 (bitwise 2-of-4 majority, zero shuffles), MLP-4 load phase, IMAD-offloaded
// accumulate in the XNOR-popcount core.
//  L0: 1x28x28 ->16x14x14 (T=4)  L1: ->16x7x7  L2: ->16x6x6
//  L3: ->16x3x3  L4: ->16x1x1 (T=64)  L5: ->10 (T=16)
//  bit=1 <=> +1 ; out bit = (#mismatch >= T/2).

#define NTHREADS 256
#define IMGS_PER_BLOCK 64            // 4 threads per image
#define NWORDS (IMGS_PER_BLOCK * 784 / 32)   // 1568
#define NCHUNKS (NWORDS / 4)                 // 392 float4-chunks
#define S1 53
#define S2 37
#define S3 13
#define FULL 0xFFFFFFFFu

__device__ __forceinline__ uint32_t nand16(uint64_t a, const uint64_t (&W)[16]) {
    const uint32_t al = (uint32_t)a, ah = (uint32_t)(a >> 32);
    uint32_t acc = 0;
#pragma unroll
    for (int oc = 0; oc < 16; oc++) {
        uint32_t xl = al ^ (uint32_t)W[oc];
        uint32_t xh = ah ^ (uint32_t)(W[oc] >> 32);
        uint32_t D = __popc(xl) + __popc(xh) + 32;   // IADD3
        uint32_t bit = D >> 6;                        // 1 iff mismatches >= 32
        asm("mad.lo.u32 %0, %1, %2, %0;" : "+r"(acc) : "r"(bit), "r"(1u << oc));
    }
    return acc;
}

// L0 cell: 2x2 patch (rows rA,rB, columns cc,cc+1) vs all 16 channels at once.
// Returns 16-bit channel vector (upper bits garbage): (#mismatch >= 2).
__device__ __forceinline__ uint32_t cell16(uint32_t rA, uint32_t rB, int cc,
                                           uint32_t W00, uint32_t W01,
                                           uint32_t W02, uint32_t W03) {
    uint32_t m0 = W00 ^ (uint32_t)(((int)(rA << (31 - cc))) >> 31);
    uint32_t m1 = W01 ^ (uint32_t)(((int)(rA << (30 - cc))) >> 31);
    uint32_t m2 = W02 ^ (uint32_t)(((int)(rB << (31 - cc))) >> 31);
    uint32_t m3 = W03 ^ (uint32_t)(((int)(rB << (30 - cc))) >> 31);
    return (m0 & m1) | (m2 & m3) | ((m0 ^ m1) & (m2 ^ m3));
}

__global__ void __launch_bounds__(NTHREADS, 3)
bnn_mnist_kernel(const float* __restrict__ x,
                 const float* __restrict__ w0, const float* __restrict__ w1,
                 const float* __restrict__ w2, const float* __restrict__ w3,
                 const float* __restrict__ w4, const float* __restrict__ w5,
                 float* __restrict__ out, int B)
{
    __shared__ uint32_t sbits[NWORDS + 1];
    __shared__ uint64_t sw_sh[4][16];
    __shared__ uint32_t sw0t[4];     // tap-k weight bit per channel (16-bit masks)
    __shared__ uint32_t sw5s[10];
    __shared__ uint32_t sact1[IMGS_PER_BLOCK * S1];
    __shared__ uint32_t sact2[IMGS_PER_BLOCK * S2];
    __shared__ uint32_t sact3[IMGS_PER_BLOCK * S3];

    const int tid = threadIdx.x;
    const int lane = tid & 31;
    const int b0 = blockIdx.x * IMGS_PER_BLOCK;

    // ---- weight prep ----
    if (tid < 64) {
        int L = tid >> 4, oc = tid & 15;
        const float* wp = (L == 0 ? w1 : L == 1 ? w2 : L == 2 ? w3 : w4) + oc * 64;
        uint64_t v = 0;
#pragma unroll
        for (int ic = 0; ic < 16; ic++)
#pragma unroll
            for (int tap = 0; tap < 4; tap++)
                if (wp[ic * 4 + tap] > 0.0f) v |= 1ull << (tap * 16 + ic);
        sw_sh[L][oc] = v;
    } else if (tid < 68) {
        int k = tid - 64;
        uint32_t v = 0;
#pragma unroll
        for (int c = 0; c < 16; c++)
            if (w0[c * 4 + k] > 0.0f) v |= 1u << c;
        sw0t[k] = v;
    } else if (tid < 78) {
        int c = tid - 68;
        uint32_t v = 0;
#pragma unroll
        for (int ic = 0; ic < 16; ic++)
            if (w5[c * 16 + ic] > 0.0f) v |= 1u << ic;
        sw5s[c] = v;
    } else if (tid == 78) {
        sbits[NWORDS] = 0;
    }

    // ---- load + binarize + pack (MLP-4: batch 4 independent LDG.128) ----
    {
        const int warp = tid >> 5;
        const float* chunk = x + (size_t)b0 * 784;
        if (b0 + IMGS_PER_BLOCK <= B) {
            const float4* c4 = (const float4*)chunk;
            // NCHUNKS = 392, divisible by 4: each warp takes 4 consecutive
            // chunks per round; all 4 valid whenever the first is.
            for (int ch0 = warp * 4; ch0 < NCHUNKS; ch0 += 32) {
                float4 v[4];
#pragma unroll
                for (int u = 0; u < 4; u++)
                    v[u] = c4[(ch0 + u) * 32 + lane];
#pragma unroll
                for (int u = 0; u < 4; u++) {
                    uint32_t nib = (uint32_t)(v[u].x > 0.0f) | ((uint32_t)(v[u].y > 0.0f) << 1)
                                 | ((uint32_t)(v[u].z > 0.0f) << 2) | ((uint32_t)(v[u].w > 0.0f) << 3);
                    uint32_t val = nib << (4 * (lane & 7));
                    val |= __shfl_xor_sync(FULL, val, 1);
                    val |= __shfl_xor_sync(FULL, val, 2);
                    val |= __shfl_xor_sync(FULL, val, 4);
                    if ((lane & 7) == 0) sbits[(ch0 + u) * 4 + (lane >> 3)] = val;
                }
            }
        } else {
            const int nfloats = max(min(IMGS_PER_BLOCK, B - b0), 0) * 784;
            for (int w = warp; w < NWORDS; w += (NTHREADS / 32)) {
                int f = w * 32 + lane;
                float v = (f < nfloats) ? chunk[f] : 0.0f;
                unsigned bb = __ballot_sync(FULL, v > 0.0f);
                if (lane == 0) sbits[w] = bb;
            }
        }
    }
    __syncthreads();

    const int sub  = tid & 3;          // 0..3: sub-worker within image
    const int limg = tid >> 2;         // 0..63: block-local image
    const int img  = b0 + limg;
    const int bitbase = limg * 784;
    const int row1 = limg * S1;
    const int row2 = limg * S2;
    const int row3 = limg * S3;

    const uint32_t W00 = sw0t[0], W01 = sw0t[1], W02 = sw0t[2], W03 = sw0t[3];

    uint64_t W[16];

    // ---- L0+L1: rows dealt {0,4},{1,5},{2,6},{3}; no shfl -> divergence OK ----
#pragma unroll
    for (int k = 0; k < 16; k++) W[k] = sw_sh[0][k];
#pragma unroll
    for (int t = 0; t < 2; t++) {
        const int i = sub + 4 * t;
        if (i < 7) {
            const int r0 = bitbase + 112 * i;   // input row 4i
            int bp = r0;
            uint32_t rA0 = __funnelshift_r(sbits[bp >> 5], sbits[(bp >> 5) + 1], bp);
            bp = r0 + 28;
            uint32_t rB0 = __funnelshift_r(sbits[bp >> 5], sbits[(bp >> 5) + 1], bp);
            bp = r0 + 56;
            uint32_t rA1 = __funnelshift_r(sbits[bp >> 5], sbits[(bp >> 5) + 1], bp);
            bp = r0 + 84;
            uint32_t rB1 = __funnelshift_r(sbits[bp >> 5], sbits[(bp >> 5) + 1], bp);
#pragma unroll
            for (int j = 0; j < 7; j++) {
                const int cc = 4 * j;
                uint32_t v00 = cell16(rA0, rB0, cc,     W00, W01, W02, W03) & 0xFFFFu;
                uint32_t v01 = cell16(rA0, rB0, cc + 2, W00, W01, W02, W03) & 0xFFFFu;
                uint32_t v10 = cell16(rA1, rB1, cc,     W00, W01, W02, W03) & 0xFFFFu;
                uint32_t v11 = cell16(rA1, rB1, cc + 2, W00, W01, W02, W03) & 0xFFFFu;
                uint64_t a64 = (uint64_t)(v00 | (v01 << 16))
                             | ((uint64_t)(v10 | (v11 << 16)) << 32);
                sact1[row1 + i * 7 + j] = nand16(a64, W);
            }
        }
    }
    __syncwarp();

    // ---- L2: 7x7 -> 6x6; 36 positions dealt p = sub + 4k (exact cover) ----
#pragma unroll
    for (int k = 0; k < 16; k++) W[k] = sw_sh[1][k];
#pragma unroll
    for (int k = 0; k < 9; k++) {
        const int p = sub + 4 * k;
        const int i = p / 6;
        const int q = row1 + p + i;      // i*7 + j
        uint64_t a64 = (uint64_t)sact1[q] | ((uint64_t)sact1[q + 1] << 16)
                     | ((uint64_t)sact1[q + 7] << 32) | ((uint64_t)sact1[q + 8] << 48);
        sact2[row2 + p] = nand16(a64, W);
    }
    __syncwarp();

    // ---- L3: 6x6 -> 3x3; 9 positions: p = sub + 4k, guard p<9 ----
#pragma unroll
    for (int k = 0; k < 16; k++) W[k] = sw_sh[2][k];
#pragma unroll
    for (int k = 0; k < 3; k++) {
        const int p = sub + 4 * k;
        if (p < 9) {
            const int i = p / 3;
            const int j = p - 3 * i;
            const int q = row2 + 12 * i + 2 * j;
            uint64_t a64 = (uint64_t)sact2[q] | ((uint64_t)sact2[q + 1] << 16)
                         | ((uint64_t)sact2[q + 6] << 32) | ((uint64_t)sact2[q + 7] << 48);
            sact3[row3 + p] = nand16(a64, W);
        }
    }
    __syncwarp();

    // ---- L4: 1 position; 4 ocs per sub, merge via shfl_xor OR ----
    uint32_t act4;
    {
        uint64_t a4 = (uint64_t)sact3[row3 + 0] | ((uint64_t)sact3[row3 + 1] << 16)
                    | ((uint64_t)sact3[row3 + 3] << 32) | ((uint64_t)sact3[row3 + 4] << 48);
        uint32_t acc = 0;
#pragma unroll
        for (int m = 0; m < 4; m++) {
            const int oc = sub * 4 + m;
            uint64_t xx = a4 ^ sw_sh[3][oc];
            uint32_t D = __popc((uint32_t)xx) + __popc((uint32_t)(xx >> 32)) + 32;
            acc |= (D >> 6) << oc;
        }
        acc |= __shfl_xor_sync(FULL, acc, 1);
        acc |= __shfl_xor_sync(FULL, acc, 2);
        act4 = acc;
    }

    // ---- L5: classes dealt per sub: {0,4,8},{1,5,9},{2,6},{3,7} ----
    if (img < B) {
        float* o = out + (size_t)img * 10;
#pragma unroll
        for (int k = 0; k < 3; k++) {
            const int oc = sub + 4 * k;
            if (oc < 10) {
                uint32_t D = __popc((act4 ^ sw5s[oc]) & 0xFFFFu);
                o[oc] = (D >= 8) ? 1.0f : -1.0f;
            }
        }
    }
}

extern "C" void kernel_launch(void* const* d_in, const int* in_sizes, int n_in,
                              void* d_out, int out_size)
{
    const float* x  = (const float*)d_in[0];
    const float* w0 = (const float*)d_in[1];
    const float* w1 = (const float*)d_in[2];
    const float* w2 = (const float*)d_in[3];
    const float* w3 = (const float*)d_in[4];
    const float* w4 = (const float*)d_in[5];
    const float* w5 = (const float*)d_in[6];
    float* out = (float*)d_out;

    int B = in_sizes[0] / 784;
    int grid = (B + IMGS_PER_BLOCK - 1) / IMGS_PER_BLOCK;
    bnn_mnist_kernel<<<grid, NTHREADS>>>(x, w0, w1, w2, w3, w4, w5, out, B);
}

// round 9
// speedup vs baseline: 1.2774x; 1.0428x over previous
#include <cuda_runtime.h>
#include <cstdint>

// Binarized NAND-conv net. WARP-AUTONOMOUS: each warp loads+packs+computes its
// own 8 images (4 threads per image) with no block-wide load/compute barrier,
// so DRAM latency of some warps overlaps popcount compute of others.
// Arithmetic L0 (bitwise 2-of-4 majority), XNOR+popcount layers.
//  L0: 1x28x28 ->16x14x14 (T=4)  L1: ->16x7x7  L2: ->16x6x6
//  L3: ->16x3x3  L4: ->16x1x1 (T=64)  L5: ->10 (T=16)
//  bit=1 <=> +1 ; out bit = (#mismatch >= T/2).

#define NTHREADS 256
#define NWARPS 8
#define IMGS_PER_WARP 8
#define IMGS_PER_BLOCK 64
#define WPW 196                       // sbits words per warp (8*784/32)
#define NWORDS (NWARPS * WPW)         // 1568
#define S1 53
#define S2 37
#define S3 13
#define FULL 0xFFFFFFFFu

__device__ __forceinline__ uint32_t nand16(uint64_t a, const uint64_t (&W)[16]) {
    const uint32_t al = (uint32_t)a, ah = (uint32_t)(a >> 32);
    uint32_t acc = 0;
#pragma unroll
    for (int oc = 0; oc < 16; oc++) {
        uint32_t xl = al ^ (uint32_t)W[oc];
        uint32_t xh = ah ^ (uint32_t)(W[oc] >> 32);
        uint32_t D = __popc(xl) + __popc(xh) + 32;
        acc |= (D >> 6) << oc;        // 1 iff mismatches >= 32 (D in [32,96])
    }
    return acc;
}

// L0 cell: 2x2 patch (rows rA,rB, columns cc,cc+1) vs all 16 channels at once.
// Returns 16-bit channel vector (upper bits garbage): (#mismatch >= 2).
// Only row bits 0..27 are ever referenced (cc+1 <= 27).
__device__ __forceinline__ uint32_t cell16(uint32_t rA, uint32_t rB, int cc,
                                           uint32_t W00, uint32_t W01,
                                           uint32_t W02, uint32_t W03) {
    uint32_t m0 = W00 ^ (uint32_t)(((int)(rA << (31 - cc))) >> 31);
    uint32_t m1 = W01 ^ (uint32_t)(((int)(rA << (30 - cc))) >> 31);
    uint32_t m2 = W02 ^ (uint32_t)(((int)(rB << (31 - cc))) >> 31);
    uint32_t m3 = W03 ^ (uint32_t)(((int)(rB << (30 - cc))) >> 31);
    return (m0 & m1) | (m2 & m3) | ((m0 ^ m1) & (m2 ^ m3));
}

__global__ void __launch_bounds__(NTHREADS, 3)
bnn_mnist_kernel(const float* __restrict__ x,
                 const float* __restrict__ w0, const float* __restrict__ w1,
                 const float* __restrict__ w2, const float* __restrict__ w3,
                 const float* __restrict__ w4, const float* __restrict__ w5,
                 float* __restrict__ out, int B)
{
    __shared__ uint32_t sbits[NWORDS + 1];   // +1 pad: overread bits unused
    __shared__ uint64_t sw_sh[4][16];
    __shared__ uint32_t sw0t[4];
    __shared__ uint32_t sw5s[10];
    __shared__ uint32_t sact1[IMGS_PER_BLOCK * S1];
    __shared__ uint32_t sact2[IMGS_PER_BLOCK * S2];
    __shared__ uint32_t sact3[IMGS_PER_BLOCK * S3];

    const int tid  = threadIdx.x;
    const int lane = tid & 31;
    const int warp = tid >> 5;
    const int b0 = blockIdx.x * IMGS_PER_BLOCK;

    // ---- weight prep (tiny; only block-wide sync in the kernel) ----
    if (tid < 64) {
        int L = tid >> 4, oc = tid & 15;
        const float* wp = (L == 0 ? w1 : L == 1 ? w2 : L == 2 ? w3 : w4) + oc * 64;
        uint64_t v = 0;
#pragma unroll
        for (int ic = 0; ic < 16; ic++)
#pragma unroll
            for (int tap = 0; tap < 4; tap++)
                if (wp[ic * 4 + tap] > 0.0f) v |= 1ull << (tap * 16 + ic);
        sw_sh[L][oc] = v;
    } else if (tid < 68) {
        int k = tid - 64;
        uint32_t v = 0;
#pragma unroll
        for (int c = 0; c < 16; c++)
            if (w0[c * 4 + k] > 0.0f) v |= 1u << c;
        sw0t[k] = v;
    } else if (tid < 78) {
        int c = tid - 68;
        uint32_t v = 0;
#pragma unroll
        for (int ic = 0; ic < 16; ic++)
            if (w5[c * 16 + ic] > 0.0f) v |= 1u << ic;
        sw5s[c] = v;
    } else if (tid == 78) {
        sbits[NWORDS] = 0;
    }
    __syncthreads();

    // ---- warp-autonomous load + binarize + pack (own 8 images) ----
    {
        // warp's float range: [warp*6272, +6272) within block chunk
        const float* chunk = x + (size_t)b0 * 784 + warp * (IMGS_PER_WARP * 784);
        const int sb = warp * WPW;
        if (b0 + IMGS_PER_BLOCK <= B) {
            const float4* c4 = (const float4*)chunk;
            // 49 warp-chunks of 128 floats; batch 7 for MLP
#pragma unroll
            for (int c0 = 0; c0 < 49; c0 += 7) {
                float4 v[7];
#pragma unroll
                for (int u = 0; u < 7; u++)
                    v[u] = c4[(c0 + u) * 32 + lane];
#pragma unroll
                for (int u = 0; u < 7; u++) {
                    uint32_t nib = (uint32_t)(v[u].x > 0.0f) | ((uint32_t)(v[u].y > 0.0f) << 1)
                                 | ((uint32_t)(v[u].z > 0.0f) << 2) | ((uint32_t)(v[u].w > 0.0f) << 3);
                    uint32_t val = nib << (4 * (lane & 7));
                    val |= __shfl_xor_sync(FULL, val, 1);
                    val |= __shfl_xor_sync(FULL, val, 2);
                    val |= __shfl_xor_sync(FULL, val, 4);
                    if ((lane & 7) == 0) sbits[sb + (c0 + u) * 4 + (lane >> 3)] = val;
                }
            }
        } else {
            const int nfl = max(min(IMGS_PER_BLOCK, B - b0), 0) * 784 - warp * (IMGS_PER_WARP * 784);
            for (int wdx = 0; wdx < WPW; wdx++) {
                int f = wdx * 32 + lane;
                float v = (f < nfl) ? chunk[f] : 0.0f;
                unsigned bb = __ballot_sync(FULL, v > 0.0f);
                if (lane == 0) sbits[sb + wdx] = bb;
            }
        }
    }
    __syncwarp();

    const int sub  = tid & 3;              // sub-worker within image
    const int limg = tid >> 2;             // block-local image = warp*8 + (lane>>2)
    const int img  = b0 + limg;
    const int bitbase = limg * 784;        // == warp*WPW*32 + (lane>>2)*784
    const int row1 = limg * S1;
    const int row2 = limg * S2;
    const int row3 = limg * S3;

    const uint32_t W00 = sw0t[0], W01 = sw0t[1], W02 = sw0t[2], W03 = sw0t[3];

    uint64_t W[16];

    // ---- L0+L1: rows dealt {0,4},{1,5},{2,6},{3} ----
#pragma unroll
    for (int k = 0; k < 16; k++) W[k] = sw_sh[0][k];
#pragma unroll
    for (int t = 0; t < 2; t++) {
        const int i = sub + 4 * t;
        if (i < 7) {
            const int r0 = bitbase + 112 * i;
            int bp = r0;
            uint32_t rA0 = __funnelshift_r(sbits[bp >> 5], sbits[(bp >> 5) + 1], bp);
            bp = r0 + 28;
            uint32_t rB0 = __funnelshift_r(sbits[bp >> 5], sbits[(bp >> 5) + 1], bp);
            bp = r0 + 56;
            uint32_t rA1 = __funnelshift_r(sbits[bp >> 5], sbits[(bp >> 5) + 1], bp);
            bp = r0 + 84;
            uint32_t rB1 = __funnelshift_r(sbits[bp >> 5], sbits[(bp >> 5) + 1], bp);
#pragma unroll
            for (int j = 0; j < 7; j++) {
                const int cc = 4 * j;
                uint32_t v00 = cell16(rA0, rB0, cc,     W00, W01, W02, W03) & 0xFFFFu;
                uint32_t v01 = cell16(rA0, rB0, cc + 2, W00, W01, W02, W03) & 0xFFFFu;
                uint32_t v10 = cell16(rA1, rB1, cc,     W00, W01, W02, W03) & 0xFFFFu;
                uint32_t v11 = cell16(rA1, rB1, cc + 2, W00, W01, W02, W03) & 0xFFFFu;
                uint64_t a64 = (uint64_t)(v00 | (v01 << 16))
                             | ((uint64_t)(v10 | (v11 << 16)) << 32);
                sact1[row1 + i * 7 + j] = nand16(a64, W);
            }
        }
    }
    __syncwarp();

    // ---- L2: 7x7 -> 6x6; p = sub + 4k (exact cover of 36) ----
#pragma unroll
    for (int k = 0; k < 16; k++) W[k] = sw_sh[1][k];
#pragma unroll
    for (int k = 0; k < 9; k++) {
        const int p = sub + 4 * k;
        const int i = p / 6;
        const int q = row1 + p + i;
        uint64_t a64 = (uint64_t)sact1[q] | ((uint64_t)sact1[q + 1] << 16)
                     | ((uint64_t)sact1[q + 7] << 32) | ((uint64_t)sact1[q + 8] << 48);
        sact2[row2 + p] = nand16(a64, W);
    }
    __syncwarp();

    // ---- L3: 6x6 -> 3x3; p = sub + 4k, guard p<9 ----
#pragma unroll
    for (int k = 0; k < 16; k++) W[k] = sw_sh[2][k];
#pragma unroll
    for (int k = 0; k < 3; k++) {
        const int p = sub + 4 * k;
        if (p < 9) {
            const int i = p / 3;
            const int j = p - 3 * i;
            const int q = row2 + 12 * i + 2 * j;
            uint64_t a64 = (uint64_t)sact2[q] | ((uint64_t)sact2[q + 1] << 16)
                         | ((uint64_t)sact2[q + 6] << 32) | ((uint64_t)sact2[q + 7] << 48);
            sact3[row3 + p] = nand16(a64, W);
        }
    }
    __syncwarp();

    // ---- L4: 4 ocs per sub, merge via shfl_xor OR (subs are adjacent lanes) ----
    uint32_t act4;
    {
        uint64_t a4 = (uint64_t)sact3[row3 + 0] | ((uint64_t)sact3[row3 + 1] << 16)
                    | ((uint64_t)sact3[row3 + 3] << 32) | ((uint64_t)sact3[row3 + 4] << 48);
        uint32_t acc = 0;
#pragma unroll
        for (int m = 0; m < 4; m++) {
            const int oc = sub * 4 + m;
            uint64_t xx = a4 ^ sw_sh[3][oc];
            uint32_t D = __popc((uint32_t)xx) + __popc((uint32_t)(xx >> 32)) + 32;
            acc |= (D >> 6) << oc;
        }
        acc |= __shfl_xor_sync(FULL, acc, 1);
        acc |= __shfl_xor_sync(FULL, acc, 2);
        act4 = acc;
    }

    // ---- L5: classes dealt per sub ----
    if (img < B) {
        float* o = out + (size_t)img * 10;
#pragma unroll
        for (int k = 0; k < 3; k++) {
            const int oc = sub + 4 * k;
            if (oc < 10) {
                uint32_t D = __popc((act4 ^ sw5s[oc]) & 0xFFFFu);
                o[oc] = (D >= 8) ? 1.0f : -1.0f;
            }
        }
    }
}

extern "C" void kernel_launch(void* const* d_in, const int* in_sizes, int n_in,
                              void* d_out, int out_size)
{
    const float* x  = (const float*)d_in[0];
    const float* w0 = (const float*)d_in[1];
    const float* w1 = (const float*)d_in[2];
    const float* w2 = (const float*)d_in[3];
    const float* w3 = (const float*)d_in[4];
    const float* w4 = (const float*)d_in[5];
    const float* w5 = (const float*)d_in[6];
    float* out = (float*)d_out;

    int B = in_sizes[0] / 784;
    int grid = (B + IMGS_PER_BLOCK - 1) / IMGS_PER_BLOCK;
    bnn_mnist_kernel<<<grid, NTHREADS>>>(x, w0, w1, w2, w3, w4, w5, out, B);
}